// round 7
// baseline (speedup 1.0000x reference)
#include <cuda_runtime.h>
#include <cuda_bf16.h>
#include <cstdint>
#include <math.h>

#define B_  8192
#define H_  1024
#define HH_ 512
#define M_  16
#define BM  128
#define BN  128
#define NTH 256
#define MARGIN_THRESH 0.03f

typedef __nv_bfloat16 bf16;

// ---------------- scratch (device globals, no allocation) ----------------
__device__ bf16  g_qhi[B_ * H_];
__device__ bf16  g_qlo[B_ * H_];
__device__ bf16  g_w1hi[HH_ * H_];
__device__ bf16  g_w1lo[HH_ * H_];
__device__ bf16  g_ew1b[M_ * HH_ * H_];
__device__ bf16  g_ew2b[M_ * H_ * HH_];
__device__ float g_X1[B_ * HH_];
__device__ bf16  g_Hb[B_ * HH_];
__device__ float g_Obuf[B_ * H_];
__device__ int   g_top[B_];
__device__ int   g_rows[M_ * B_];
__device__ int   g_cnt[M_];
__device__ int   g_flag[B_];
__device__ int   g_nflag;

// ---------------- PTX helpers (all sm_80-compatible) ----------------
__device__ __forceinline__ uint32_t smem_u32(const void* p) {
    uint32_t a;
    asm("{ .reg .u64 t; cvta.to.shared.u64 t, %1; cvt.u32.u64 %0, t; }" : "=r"(a) : "l"(p));
    return a;
}
__device__ __forceinline__ void cp16(uint32_t dst, const void* src) {
    asm volatile("cp.async.cg.shared.global [%0], [%1], 16;" :: "r"(dst), "l"(src));
}
__device__ __forceinline__ void cp_commit() { asm volatile("cp.async.commit_group;" ::: "memory"); }
template <int N> __device__ __forceinline__ void cp_wait() {
    asm volatile("cp.async.wait_group %0;" :: "n"(N) : "memory");
}
__device__ __forceinline__ void ldmx4(uint32_t* r, uint32_t addr) {
    asm volatile("ldmatrix.sync.aligned.m8n8.x4.shared.b16 {%0,%1,%2,%3}, [%4];"
                 : "=r"(r[0]), "=r"(r[1]), "=r"(r[2]), "=r"(r[3]) : "r"(addr));
}
__device__ __forceinline__ void mma16816(float* d, const uint32_t* a, const uint32_t* b) {
    asm volatile(
        "mma.sync.aligned.m16n8k16.row.col.f32.bf16.bf16.f32 "
        "{%0,%1,%2,%3}, {%4,%5,%6,%7}, {%8,%9}, {%0,%1,%2,%3};"
        : "+f"(d[0]), "+f"(d[1]), "+f"(d[2]), "+f"(d[3])
        : "r"(a[0]), "r"(a[1]), "r"(a[2]), "r"(a[3]), "r"(b[0]), "r"(b[1]));
}

// ---------------- conversion kernels (16 elems / thread) -------
__global__ void split16_k(const float* __restrict__ x, bf16* __restrict__ hi,
                          bf16* __restrict__ lo, int n) {
    int i = (blockIdx.x * blockDim.x + threadIdx.x) * 16;
    if (i >= n) return;
    float4 v[4];
#pragma unroll
    for (int c = 0; c < 4; c++) v[c] = *(const float4*)(x + i + c * 4);
    const float* vv = (const float*)v;
    __nv_bfloat162 hp[8], lp[8];
#pragma unroll
    for (int j = 0; j < 8; j++) {
        bf16 h0 = __float2bfloat16_rn(vv[2*j]);
        bf16 h1 = __float2bfloat16_rn(vv[2*j+1]);
        hp[j] = __nv_bfloat162(h0, h1);
        lp[j] = __nv_bfloat162(__float2bfloat16_rn(vv[2*j]   - __bfloat162float(h0)),
                               __float2bfloat16_rn(vv[2*j+1] - __bfloat162float(h1)));
    }
    *(uint4*)(hi + i)     = ((uint4*)hp)[0];
    *(uint4*)(hi + i + 8) = ((uint4*)hp)[1];
    *(uint4*)(lo + i)     = ((uint4*)lp)[0];
    *(uint4*)(lo + i + 8) = ((uint4*)lp)[1];
}

__global__ void cvt16_k(const float* __restrict__ x, bf16* __restrict__ y, int n) {
    int i = (blockIdx.x * blockDim.x + threadIdx.x) * 16;
    if (i >= n) return;
    float4 v[4];
#pragma unroll
    for (int c = 0; c < 4; c++) v[c] = *(const float4*)(x + i + c * 4);
    const float* vv = (const float*)v;
    __nv_bfloat162 p[8];
#pragma unroll
    for (int j = 0; j < 8; j++)
        p[j] = __nv_bfloat162(__float2bfloat16_rn(vv[2*j]), __float2bfloat16_rn(vv[2*j+1]));
    *(uint4*)(y + i)     = ((uint4*)p)[0];
    *(uint4*)(y + i + 8) = ((uint4*)p)[1];
}

// ---------------- HMMA GEMM: C[i,n] = act(sum_k A[i,k]*W[n,k] + b[n]) ----
// SPLIT=0: 3-stage cp.async pipeline, 97.3KB smem -> 2 CTAs/SM (16 warps/SM).
// SPLIT=1: 3-pass hi/lo bf16 (near-fp32), 2-stage loop (rare, small grid).
// GROUPED: 0 = plain rows, 1 = per-expert (g_rows/g_cnt, blockIdx.z),
//          2 = flagged rows (g_flag/g_nflag).
template <int SPLIT, int GROUPED, int RELU, typename OutT>
__global__ __launch_bounds__(NTH, 2)
void gemm_mma(const bf16* __restrict__ Ahi, const bf16* __restrict__ Alo,
              const bf16* __restrict__ Whi, const bf16* __restrict__ Wlo,
              const float* __restrict__ bias, OutT* __restrict__ C,
              int N, int K, int plain_rows)
{
    int e = (GROUPED == 1) ? blockIdx.z : 0;
    int nrows = (GROUPED == 1) ? g_cnt[e] : (GROUPED == 2) ? g_nflag : plain_rows;
    int row0 = blockIdx.x * BM;
    if (row0 >= nrows) return;
    int col0 = blockIdx.y * BN;

    const bf16*  Wh = Whi + ((GROUPED == 1) ? (size_t)e * N * K : 0);
    const bf16*  Wl = Wlo + ((GROUPED == 1) ? (size_t)e * N * K : 0);
    const float* bp = bias + ((GROUPED == 1) ? (size_t)e * N : 0);

    extern __shared__ char smem[];
    int*   srow  = (int*)smem;            // [128]
    float* sbias = (float*)(smem + 512);  // [128]
    constexpr int HDR  = 1024;
    constexpr int TILE = BM * 128;        // 16KB per operand tile

    int t = threadIdx.x;
    if (t < BM) {
        int gr = row0 + t;
        int cr = gr < nrows ? gr : nrows - 1;
        srow[t] = (GROUPED == 1) ? g_rows[e * B_ + cr]
                : (GROUPED == 2) ? g_flag[cr] : cr;
    }
    if (t < BN) sbias[t] = bp[col0 + t];
    __syncthreads();

    uint32_t sb = smem_u32(smem) + HDR;

    // loader: thread t -> row t>>1, 16B chunks (t&1)*4 .. +3
    const int lrow = t >> 1, lhalf = (t & 1) * 4, lx7 = lrow & 7;
    const int nc = K >> 6;
    const size_t arow = (size_t)srow[lrow] * K;
    const size_t wrow = (size_t)(col0 + lrow) * K;

    const int wid = t >> 5, lane = t & 31;
    const int wm = (wid & 1) * 64;   // warp row offset
    const int wn = (wid >> 1) * 32;  // warp col offset
    const int rb = lane & 15, csel = lane >> 4, x7 = rb & 7;

    float acc[4][4][4];
#pragma unroll
    for (int i = 0; i < 4; i++)
#pragma unroll
        for (int j = 0; j < 4; j++)
#pragma unroll
            for (int q = 0; q < 4; q++) acc[i][j][q] = 0.0f;

    uint32_t arow_b[4], wrow_b[2];
#pragma unroll
    for (int mi = 0; mi < 4; mi++) arow_b[mi] = (wm + mi * 16 + rb) * 128;
#pragma unroll
    for (int nb = 0; nb < 2; nb++) wrow_b[nb] = (wn + nb * 16 + rb) * 128;

    if constexpr (!SPLIT) {
        // ---------- fast path: 3-stage ring, 2 CTAs/SM ----------
        // stage s = c % 3, each stage = A tile + W tile (32 KB)
        auto stA = [&](int c) {
            int s = c % 3;
            return sb + (uint32_t)s * (2 * TILE);
        };
        auto issueN = [&](int c) {
            uint32_t st = stA(c);
            size_t koff = (size_t)c * 64 + lhalf * 8;
#pragma unroll
            for (int j = 0; j < 4; j++) {
                uint32_t doff = lrow * 128 + (((lhalf + j) ^ lx7) * 16);
                cp16(st + doff, Ahi + arow + koff + j * 8);
                cp16(st + TILE + doff, Wh + wrow + koff + j * 8);
            }
            cp_commit();
        };

        issueN(0); issueN(1);
        cp_wait<1>();
        __syncthreads();

        for (int c = 0; c < nc; c++) {
            uint32_t st = stA(c);
#pragma unroll
            for (int ks = 0; ks < 4; ks++) {
                uint32_t ksel = (uint32_t)((2 * ks + csel) ^ x7) * 16;
                uint32_t ah[4][4], bh[4][2];
#pragma unroll
                for (int mi = 0; mi < 4; mi++)
                    ldmx4(ah[mi], st + arow_b[mi] + ksel);
#pragma unroll
                for (int nb = 0; nb < 2; nb++) {
                    uint32_t r[4];
                    ldmx4(r, st + TILE + wrow_b[nb] + ksel);
                    bh[2 * nb][0] = r[0]; bh[2 * nb + 1][0] = r[1];
                    bh[2 * nb][1] = r[2]; bh[2 * nb + 1][1] = r[3];
                }
#pragma unroll
                for (int mi = 0; mi < 4; mi++)
#pragma unroll
                    for (int ni = 0; ni < 4; ni++)
                        mma16816(acc[mi][ni], ah[mi], bh[ni]);
            }
            __syncthreads();               // all warps done reading stage c%3
            if (c + 2 < nc) issueN(c + 2); // reuses stage (c-1)%3 — safe
            else            cp_commit();
            cp_wait<1>();                  // chunk c+1 complete
            __syncthreads();
        }
    } else {
        // ---------- split path (rare): 2-stage, 4 tiles/stage ----------
        constexpr int STAGE = 4 * TILE;
        constexpr int AHI = 0, ALO = TILE, WHI = 2 * TILE, WLO = 3 * TILE;
        auto issue = [&](int c) {
            uint32_t st = sb + (c & 1) * STAGE;
            size_t koff = (size_t)c * 64 + lhalf * 8;
#pragma unroll
            for (int j = 0; j < 4; j++) {
                uint32_t doff = lrow * 128 + (((lhalf + j) ^ lx7) * 16);
                cp16(st + AHI + doff, Ahi + arow + koff + j * 8);
                cp16(st + WHI + doff, Wh  + wrow + koff + j * 8);
                cp16(st + ALO + doff, Alo + arow + koff + j * 8);
                cp16(st + WLO + doff, Wl  + wrow + koff + j * 8);
            }
            cp_commit();
        };

        issue(0); issue(1);
        cp_wait<1>();
        __syncthreads();

        for (int c = 0; c < nc; c++) {
            uint32_t st = sb + (c & 1) * STAGE;
#pragma unroll
            for (int ks = 0; ks < 4; ks++) {
                uint32_t ksel = (uint32_t)((2 * ks + csel) ^ x7) * 16;
                uint32_t ah[4][4], bh[4][2];
#pragma unroll
                for (int mi = 0; mi < 4; mi++)
                    ldmx4(ah[mi], st + AHI + arow_b[mi] + ksel);
#pragma unroll
                for (int nb = 0; nb < 2; nb++) {
                    uint32_t r[4];
                    ldmx4(r, st + WHI + wrow_b[nb] + ksel);
                    bh[2 * nb][0] = r[0]; bh[2 * nb + 1][0] = r[1];
                    bh[2 * nb][1] = r[2]; bh[2 * nb + 1][1] = r[3];
                }
#pragma unroll
                for (int mi = 0; mi < 4; mi++)
#pragma unroll
                    for (int ni = 0; ni < 4; ni++)
                        mma16816(acc[mi][ni], ah[mi], bh[ni]);
                uint32_t al[4][4], bl[4][2];
#pragma unroll
                for (int mi = 0; mi < 4; mi++)
                    ldmx4(al[mi], st + ALO + arow_b[mi] + ksel);
#pragma unroll
                for (int nb = 0; nb < 2; nb++) {
                    uint32_t r[4];
                    ldmx4(r, st + WLO + wrow_b[nb] + ksel);
                    bl[2 * nb][0] = r[0]; bl[2 * nb + 1][0] = r[1];
                    bl[2 * nb][1] = r[2]; bl[2 * nb + 1][1] = r[3];
                }
#pragma unroll
                for (int mi = 0; mi < 4; mi++)
#pragma unroll
                    for (int ni = 0; ni < 4; ni++) {
                        mma16816(acc[mi][ni], ah[mi], bl[ni]);
                        mma16816(acc[mi][ni], al[mi], bh[ni]);
                    }
            }
            __syncthreads();
            if (c + 2 < nc) issue(c + 2);
            else            cp_commit();
            cp_wait<1>();
            __syncthreads();
        }
    }

    // epilogue
    const int lr4 = lane >> 2, lc2 = 2 * (lane & 3);
#pragma unroll
    for (int mi = 0; mi < 4; mi++) {
        int r0i = wm + mi * 16 + lr4;
        int r1i = r0i + 8;
        bool v0 = (row0 + r0i) < nrows;
        bool v1 = (row0 + r1i) < nrows;
        size_t g0 = (size_t)srow[r0i] * N + col0;
        size_t g1 = (size_t)srow[r1i] * N + col0;
#pragma unroll
        for (int ni = 0; ni < 4; ni++) {
            int cc = wn + ni * 8 + lc2;
            float ba = sbias[cc], bb = sbias[cc + 1];
            float x0 = acc[mi][ni][0] + ba, x1 = acc[mi][ni][1] + bb;
            float y0 = acc[mi][ni][2] + ba, y1 = acc[mi][ni][3] + bb;
            if (RELU) {
                x0 = fmaxf(x0, 0.0f); x1 = fmaxf(x1, 0.0f);
                y0 = fmaxf(y0, 0.0f); y1 = fmaxf(y1, 0.0f);
            }
            if (sizeof(OutT) == 4) {
                if (v0) *(float2*)((float*)C + g0 + cc) = make_float2(x0, x1);
                if (v1) *(float2*)((float*)C + g1 + cc) = make_float2(y0, y1);
            } else {
                uint32_t p0, p1;
                asm("cvt.rn.bf16x2.f32 %0, %1, %2;" : "=r"(p0) : "f"(x1), "f"(x0));
                asm("cvt.rn.bf16x2.f32 %0, %1, %2;" : "=r"(p1) : "f"(y1), "f"(y0));
                if (v0) *(uint32_t*)((bf16*)C + g0 + cc) = p0;
                if (v1) *(uint32_t*)((bf16*)C + g1 + cc) = p1;
            }
        }
    }
}

// --------- logits + argmax with margin flagging -------------------------
__global__ void logits_argmax_kernel(const float* __restrict__ W3,
                                     const float* __restrict__ b3)
{
    __shared__ float sW[M_ * HH_];
    __shared__ float sb[M_];
    for (int i = threadIdx.x; i < M_ * HH_; i += blockDim.x) sW[i] = W3[i];
    if (threadIdx.x < M_) sb[threadIdx.x] = b3[threadIdx.x];
    __syncthreads();

    int gw   = (blockIdx.x * blockDim.x + threadIdx.x) >> 5;
    int lane = threadIdx.x & 31;
    int nw   = (gridDim.x * blockDim.x) >> 5;

    for (int row = gw; row < B_; row += nw) {
        const float* x = g_X1 + (size_t)row * HH_;
        float xv[16];
#pragma unroll
        for (int tt = 0; tt < 16; tt++) xv[tt] = x[lane + 32 * tt];
        float best = -3.0e38f, second = -3.0e38f;
        int   bi   = 0;
#pragma unroll
        for (int m = 0; m < M_; m++) {
            float p = 0.0f;
            const float* wrow = sW + m * HH_;
#pragma unroll
            for (int tt = 0; tt < 16; tt++)
                p = fmaf(xv[tt], wrow[lane + 32 * tt], p);
#pragma unroll
            for (int o = 16; o; o >>= 1) p += __shfl_xor_sync(0xffffffffu, p, o);
            p += sb[m];
            if (p > best) { second = best; best = p; bi = m; }
            else if (p > second) second = p;
        }
        if (lane == 0) {
            g_top[row] = bi;
            if (best - second < MARGIN_THRESH) {
                int fp = atomicAdd(&g_nflag, 1);
                g_flag[fp] = row;
            }
        }
    }
}

// --------- fix argmax for flagged rows (their X1 is now exact) ----------
__global__ void logits_fix_kernel(const float* __restrict__ W3,
                                  const float* __restrict__ b3)
{
    __shared__ float sW[M_ * HH_];
    __shared__ float sb[M_];
    for (int i = threadIdx.x; i < M_ * HH_; i += blockDim.x) sW[i] = W3[i];
    if (threadIdx.x < M_) sb[threadIdx.x] = b3[threadIdx.x];
    __syncthreads();

    int gw   = (blockIdx.x * blockDim.x + threadIdx.x) >> 5;
    int lane = threadIdx.x & 31;
    int nw   = (gridDim.x * blockDim.x) >> 5;
    int nf   = g_nflag;

    for (int idx = gw; idx < nf; idx += nw) {
        int row = g_flag[idx];
        const float* x = g_X1 + (size_t)row * HH_;
        float xv[16];
#pragma unroll
        for (int tt = 0; tt < 16; tt++) xv[tt] = x[lane + 32 * tt];
        float best = -3.0e38f;
        int   bi   = 0;
#pragma unroll
        for (int m = 0; m < M_; m++) {
            float p = 0.0f;
            const float* wrow = sW + m * HH_;
#pragma unroll
            for (int tt = 0; tt < 16; tt++)
                p = fmaf(xv[tt], wrow[lane + 32 * tt], p);
#pragma unroll
            for (int o = 16; o; o >>= 1) p += __shfl_xor_sync(0xffffffffu, p, o);
            p += sb[m];
            if (p > best) { best = p; bi = m; }
        }
        if (lane == 0) g_top[row] = bi;
    }
}

__global__ void zero_kernel() {
    if (threadIdx.x < M_) g_cnt[threadIdx.x] = 0;
    if (threadIdx.x == M_) g_nflag = 0;
}

__global__ void scatter_kernel() {
    int b = blockIdx.x * blockDim.x + threadIdx.x;
    if (b < B_) {
        int m = g_top[b];
        int p = atomicAdd(&g_cnt[m], 1);
        g_rows[m * B_ + p] = b;
    }
}

// normalize(g*v) == v / max(||v||,eps) for gate g > 0 (top-1 prob >= 1/16)
__global__ void finalize_kernel(const float* __restrict__ Q, float* __restrict__ out)
{
    int row = blockIdx.x;
    const float* o = g_Obuf + (size_t)row * H_;
    float s = 0.0f;
    for (int i = threadIdx.x; i < H_; i += 256) { float v = o[i]; s = fmaf(v, v, s); }
#pragma unroll
    for (int off = 16; off; off >>= 1) s += __shfl_xor_sync(0xffffffffu, s, off);
    __shared__ float red[8];
    if ((threadIdx.x & 31) == 0) red[threadIdx.x >> 5] = s;
    __syncthreads();
    float tot = 0.0f;
#pragma unroll
    for (int w = 0; w < 8; w++) tot += red[w];
    float inv = 1.0f / fmaxf(sqrtf(tot), 1e-6f);

    const float* qr = Q + (size_t)row * H_;
    float* orow = out + (size_t)row * H_;
    for (int i = threadIdx.x; i < H_; i += 256)
        orow[i] = fmaf(o[i], inv, qr[i]);
}

// ---------------- launch ----------------
extern "C" void kernel_launch(void* const* d_in, const int* in_sizes, int n_in,
                              void* d_out, int out_size)
{
    const float* q   = (const float*)d_in[0];
    const float* c1w = (const float*)d_in[1];
    const float* c1b = (const float*)d_in[2];
    const float* c3w = (const float*)d_in[3];
    const float* c3b = (const float*)d_in[4];
    const float* ew1 = (const float*)d_in[5];
    const float* eb1 = (const float*)d_in[6];
    const float* ew2 = (const float*)d_in[7];
    const float* eb2 = (const float*)d_in[8];
    float* out = (float*)d_out;

    void *pqh, *pql, *pw1h, *pw1l, *pe1, *pe2, *pX1, *pHb, *pO;
    cudaGetSymbolAddress(&pqh,  g_qhi);
    cudaGetSymbolAddress(&pql,  g_qlo);
    cudaGetSymbolAddress(&pw1h, g_w1hi);
    cudaGetSymbolAddress(&pw1l, g_w1lo);
    cudaGetSymbolAddress(&pe1,  g_ew1b);
    cudaGetSymbolAddress(&pe2,  g_ew2b);
    cudaGetSymbolAddress(&pX1,  g_X1);
    cudaGetSymbolAddress(&pHb,  g_Hb);
    cudaGetSymbolAddress(&pO,   g_Obuf);

    constexpr int SMEM_FAST  = 1024 + 3 * 2 * BM * 128;  // 99328  (2 CTAs/SM)
    constexpr int SMEM_SPLIT = 1024 + 2 * 4 * BM * 128;  // 132096 (1 CTA/SM)

    cudaFuncSetAttribute(gemm_mma<0, 0, 1, float>,
                         cudaFuncAttributeMaxDynamicSharedMemorySize, SMEM_FAST);
    cudaFuncSetAttribute(gemm_mma<1, 2, 1, float>,
                         cudaFuncAttributeMaxDynamicSharedMemorySize, SMEM_SPLIT);
    cudaFuncSetAttribute(gemm_mma<0, 1, 1, bf16>,
                         cudaFuncAttributeMaxDynamicSharedMemorySize, SMEM_FAST);
    cudaFuncSetAttribute(gemm_mma<0, 1, 0, float>,
                         cudaFuncAttributeMaxDynamicSharedMemorySize, SMEM_FAST);

    // launch order arranged so the 6th launch is the gating GEMM (ncu -s 5 -c 1)
    zero_kernel<<<1, 32>>>();                                                  // 1
    split16_k<<<B_ * H_ / 16 / 256, 256>>>(q, (bf16*)pqh, (bf16*)pql, B_ * H_);       // 2
    split16_k<<<HH_ * H_ / 16 / 256, 256>>>(c1w, (bf16*)pw1h, (bf16*)pw1l, HH_ * H_); // 3
    cvt16_k<<<M_ * HH_ * H_ / 16 / 256, 256>>>(ew1, (bf16*)pe1, M_ * HH_ * H_);       // 4
    cvt16_k<<<M_ * H_ * HH_ / 16 / 256, 256>>>(ew2, (bf16*)pe2, M_ * H_ * HH_);       // 5

    // 6) gating hidden, single-pass bf16: X1 = relu(Q @ c1w^T + b)
    gemm_mma<0, 0, 1, float><<<dim3(B_ / BM, HH_ / BN, 1), NTH, SMEM_FAST>>>(
        (const bf16*)pqh, nullptr, (const bf16*)pw1h, nullptr,
        c1b, (float*)pX1, HH_, H_, B_);

    // logits + argmax with margin flagging
    logits_argmax_kernel<<<64, 256>>>(c3w, c3b);

    // exact (split 3-pass) X1 recompute for flagged rows only
    gemm_mma<1, 2, 1, float><<<dim3(B_ / BM, HH_ / BN, 1), NTH, SMEM_SPLIT>>>(
        (const bf16*)pqh, (const bf16*)pql, (const bf16*)pw1h, (const bf16*)pw1l,
        c1b, (float*)pX1, HH_, H_, 0);
    logits_fix_kernel<<<32, 256>>>(c3w, c3b);

    // bucket rows by expert
    scatter_kernel<<<B_ / 256, 256>>>();

    // expert hidden: H = relu(Qg @ ew1[m]^T + b1[m])  (bf16 out)
    gemm_mma<0, 1, 1, bf16><<<dim3(B_ / BM, HH_ / BN, M_), NTH, SMEM_FAST>>>(
        (const bf16*)pqh, nullptr, (const bf16*)pe1, nullptr,
        eb1, (bf16*)pHb, HH_, H_, 0);

    // expert out: O = Hg @ ew2[m]^T + b2[m]  (fp32 out)
    gemm_mma<0, 1, 0, float><<<dim3(B_ / BM, H_ / BN, M_), NTH, SMEM_FAST>>>(
        (const bf16*)pHb, nullptr, (const bf16*)pe2, nullptr,
        eb2, (float*)pO, H_, HH_, 0);

    // out = normalize(O) + Q
    finalize_kernel<<<B_, 256>>>(q, out);
}

// round 8
// speedup vs baseline: 1.0185x; 1.0185x over previous
#include <cuda_runtime.h>
#include <cuda_bf16.h>
#include <cstdint>
#include <math.h>

#define B_  8192
#define H_  1024
#define HH_ 512
#define M_  16
#define BM  128
#define BN  128
#define NTH 256
#define MARGIN_THRESH 0.03f

typedef __nv_bfloat16 bf16;

// ---------------- scratch (device globals, no allocation) ----------------
__device__ bf16  g_qhi[B_ * H_];
__device__ bf16  g_qlo[B_ * H_];          // filled only for flagged rows
__device__ bf16  g_w1hi[HH_ * H_];
__device__ bf16  g_w1lo[HH_ * H_];
__device__ bf16  g_ew1b[M_ * HH_ * H_];
__device__ bf16  g_ew2b[M_ * H_ * HH_];
__device__ float g_X1[B_ * HH_];
__device__ bf16  g_Hb[B_ * HH_];
__device__ bf16  g_Ob16[B_ * H_];
__device__ int   g_rows[M_ * B_];
__device__ int   g_cnt[M_];
__device__ int   g_flag[B_];
__device__ int   g_nflag;

// ---------------- PTX helpers (all sm_80-compatible) ----------------
__device__ __forceinline__ uint32_t smem_u32(const void* p) {
    uint32_t a;
    asm("{ .reg .u64 t; cvta.to.shared.u64 t, %1; cvt.u32.u64 %0, t; }" : "=r"(a) : "l"(p));
    return a;
}
__device__ __forceinline__ void cp16(uint32_t dst, const void* src) {
    asm volatile("cp.async.cg.shared.global [%0], [%1], 16;" :: "r"(dst), "l"(src));
}
__device__ __forceinline__ void cp_commit() { asm volatile("cp.async.commit_group;" ::: "memory"); }
template <int N> __device__ __forceinline__ void cp_wait() {
    asm volatile("cp.async.wait_group %0;" :: "n"(N) : "memory");
}
__device__ __forceinline__ void ldmx4(uint32_t* r, uint32_t addr) {
    asm volatile("ldmatrix.sync.aligned.m8n8.x4.shared.b16 {%0,%1,%2,%3}, [%4];"
                 : "=r"(r[0]), "=r"(r[1]), "=r"(r[2]), "=r"(r[3]) : "r"(addr));
}
__device__ __forceinline__ void mma16816(float* d, const uint32_t* a, const uint32_t* b) {
    asm volatile(
        "mma.sync.aligned.m16n8k16.row.col.f32.bf16.bf16.f32 "
        "{%0,%1,%2,%3}, {%4,%5,%6,%7}, {%8,%9}, {%0,%1,%2,%3};"
        : "+f"(d[0]), "+f"(d[1]), "+f"(d[2]), "+f"(d[3])
        : "r"(a[0]), "r"(a[1]), "r"(a[2]), "r"(a[3]), "r"(b[0]), "r"(b[1]));
}

// ---------------- conversion kernels (16 elems / thread) -------
__global__ void split16_k(const float* __restrict__ x, bf16* __restrict__ hi,
                          bf16* __restrict__ lo, int n) {
    int i = (blockIdx.x * blockDim.x + threadIdx.x) * 16;
    if (i >= n) return;
    float4 v[4];
#pragma unroll
    for (int c = 0; c < 4; c++) v[c] = *(const float4*)(x + i + c * 4);
    const float* vv = (const float*)v;
    __nv_bfloat162 hp[8], lp[8];
#pragma unroll
    for (int j = 0; j < 8; j++) {
        bf16 h0 = __float2bfloat16_rn(vv[2*j]);
        bf16 h1 = __float2bfloat16_rn(vv[2*j+1]);
        hp[j] = __nv_bfloat162(h0, h1);
        lp[j] = __nv_bfloat162(__float2bfloat16_rn(vv[2*j]   - __bfloat162float(h0)),
                               __float2bfloat16_rn(vv[2*j+1] - __bfloat162float(h1)));
    }
    *(uint4*)(hi + i)     = ((uint4*)hp)[0];
    *(uint4*)(hi + i + 8) = ((uint4*)hp)[1];
    *(uint4*)(lo + i)     = ((uint4*)lp)[0];
    *(uint4*)(lo + i + 8) = ((uint4*)lp)[1];
}

__global__ void cvt16_k(const float* __restrict__ x, bf16* __restrict__ y, int n) {
    int i = (blockIdx.x * blockDim.x + threadIdx.x) * 16;
    if (i >= n) return;
    float4 v[4];
#pragma unroll
    for (int c = 0; c < 4; c++) v[c] = *(const float4*)(x + i + c * 4);
    const float* vv = (const float*)v;
    __nv_bfloat162 p[8];
#pragma unroll
    for (int j = 0; j < 8; j++)
        p[j] = __nv_bfloat162(__float2bfloat16_rn(vv[2*j]), __float2bfloat16_rn(vv[2*j+1]));
    *(uint4*)(y + i)     = ((uint4*)p)[0];
    *(uint4*)(y + i + 8) = ((uint4*)p)[1];
}

// qlo for flagged rows only: lo = q - bf16(q)
__global__ void qlo_flag_k(const float* __restrict__ q) {
    int nf = g_nflag;
    int total = nf * (H_ / 16);                 // 16 elems per work item
    for (int w = blockIdx.x * blockDim.x + threadIdx.x; w < total;
         w += gridDim.x * blockDim.x) {
        int row = g_flag[w / (H_ / 16)];
        int col = (w % (H_ / 16)) * 16;
        const float* src = q + (size_t)row * H_ + col;
        const bf16*  hi  = g_qhi + (size_t)row * H_ + col;
        bf16*        lo  = g_qlo + (size_t)row * H_ + col;
        float4 v[4];
#pragma unroll
        for (int c = 0; c < 4; c++) v[c] = *(const float4*)(src + c * 4);
        uint4 hbits[2];
        hbits[0] = *(const uint4*)hi; hbits[1] = *(const uint4*)(hi + 8);
        const float* vv = (const float*)v;
        const bf16* hh = (const bf16*)hbits;
        __nv_bfloat162 lp[8];
#pragma unroll
        for (int j = 0; j < 8; j++)
            lp[j] = __nv_bfloat162(
                __float2bfloat16_rn(vv[2*j]   - __bfloat162float(hh[2*j])),
                __float2bfloat16_rn(vv[2*j+1] - __bfloat162float(hh[2*j+1])));
        *(uint4*)lo       = ((uint4*)lp)[0];
        *(uint4*)(lo + 8) = ((uint4*)lp)[1];
    }
}

// ---------------- HMMA GEMM: C[i,n] = act(sum_k A[i,k]*W[n,k] + b[n]) ----
// SPLIT=0: 3-stage cp.async pipeline. SPLIT=1: 3-pass hi/lo (rare).
// GROUPED: 0 plain, 1 per-expert (g_rows/g_cnt, blockIdx.z), 2 flagged rows.
template <int SPLIT, int GROUPED, int RELU, typename OutT>
__global__ __launch_bounds__(NTH, 2)
void gemm_mma(const bf16* __restrict__ Ahi, const bf16* __restrict__ Alo,
              const bf16* __restrict__ Whi, const bf16* __restrict__ Wlo,
              const float* __restrict__ bias, OutT* __restrict__ C,
              int N, int K, int plain_rows)
{
    int e = (GROUPED == 1) ? blockIdx.z : 0;
    int nrows = (GROUPED == 1) ? g_cnt[e] : (GROUPED == 2) ? g_nflag : plain_rows;
    int row0 = blockIdx.x * BM;
    if (row0 >= nrows) return;
    int col0 = blockIdx.y * BN;

    const bf16*  Wh = Whi + ((GROUPED == 1) ? (size_t)e * N * K : 0);
    const bf16*  Wl = Wlo + ((GROUPED == 1) ? (size_t)e * N * K : 0);
    const float* bp = bias + ((GROUPED == 1) ? (size_t)e * N : 0);

    extern __shared__ char smem[];
    int*   srow  = (int*)smem;
    float* sbias = (float*)(smem + 512);
    constexpr int HDR  = 1024;
    constexpr int TILE = BM * 128;

    int t = threadIdx.x;
    if (t < BM) {
        int gr = row0 + t;
        int cr = gr < nrows ? gr : nrows - 1;
        srow[t] = (GROUPED == 1) ? g_rows[e * B_ + cr]
                : (GROUPED == 2) ? g_flag[cr] : cr;
    }
    if (t < BN) sbias[t] = bp[col0 + t];
    __syncthreads();

    uint32_t sb = smem_u32(smem) + HDR;

    const int lrow = t >> 1, lhalf = (t & 1) * 4, lx7 = lrow & 7;
    const int nc = K >> 6;
    const size_t arow = (size_t)srow[lrow] * K;
    const size_t wrow = (size_t)(col0 + lrow) * K;

    const int wid = t >> 5, lane = t & 31;
    const int wm = (wid & 1) * 64;
    const int wn = (wid >> 1) * 32;
    const int rb = lane & 15, csel = lane >> 4, x7 = rb & 7;

    float acc[4][4][4];
#pragma unroll
    for (int i = 0; i < 4; i++)
#pragma unroll
        for (int j = 0; j < 4; j++)
#pragma unroll
            for (int q = 0; q < 4; q++) acc[i][j][q] = 0.0f;

    uint32_t arow_b[4], wrow_b[2];
#pragma unroll
    for (int mi = 0; mi < 4; mi++) arow_b[mi] = (wm + mi * 16 + rb) * 128;
#pragma unroll
    for (int nb = 0; nb < 2; nb++) wrow_b[nb] = (wn + nb * 16 + rb) * 128;

    if constexpr (!SPLIT) {
        auto stA = [&](int c) { return sb + (uint32_t)(c % 3) * (2 * TILE); };
        auto issueN = [&](int c) {
            uint32_t st = stA(c);
            size_t koff = (size_t)c * 64 + lhalf * 8;
#pragma unroll
            for (int j = 0; j < 4; j++) {
                uint32_t doff = lrow * 128 + (((lhalf + j) ^ lx7) * 16);
                cp16(st + doff, Ahi + arow + koff + j * 8);
                cp16(st + TILE + doff, Wh + wrow + koff + j * 8);
            }
            cp_commit();
        };

        issueN(0); issueN(1);
        cp_wait<1>();
        __syncthreads();

        for (int c = 0; c < nc; c++) {
            uint32_t st = stA(c);
#pragma unroll
            for (int ks = 0; ks < 4; ks++) {
                uint32_t ksel = (uint32_t)((2 * ks + csel) ^ x7) * 16;
                uint32_t ah[4][4], bh[4][2];
#pragma unroll
                for (int mi = 0; mi < 4; mi++)
                    ldmx4(ah[mi], st + arow_b[mi] + ksel);
#pragma unroll
                for (int nb = 0; nb < 2; nb++) {
                    uint32_t r[4];
                    ldmx4(r, st + TILE + wrow_b[nb] + ksel);
                    bh[2 * nb][0] = r[0]; bh[2 * nb + 1][0] = r[1];
                    bh[2 * nb][1] = r[2]; bh[2 * nb + 1][1] = r[3];
                }
#pragma unroll
                for (int mi = 0; mi < 4; mi++)
#pragma unroll
                    for (int ni = 0; ni < 4; ni++)
                        mma16816(acc[mi][ni], ah[mi], bh[ni]);
            }
            __syncthreads();
            if (c + 2 < nc) issueN(c + 2);
            else            cp_commit();
            cp_wait<1>();
            __syncthreads();
        }
    } else {
        constexpr int STAGE = 4 * TILE;
        constexpr int AHI = 0, ALO = TILE, WHI = 2 * TILE, WLO = 3 * TILE;
        auto issue = [&](int c) {
            uint32_t st = sb + (c & 1) * STAGE;
            size_t koff = (size_t)c * 64 + lhalf * 8;
#pragma unroll
            for (int j = 0; j < 4; j++) {
                uint32_t doff = lrow * 128 + (((lhalf + j) ^ lx7) * 16);
                cp16(st + AHI + doff, Ahi + arow + koff + j * 8);
                cp16(st + WHI + doff, Wh  + wrow + koff + j * 8);
                cp16(st + ALO + doff, Alo + arow + koff + j * 8);
                cp16(st + WLO + doff, Wl  + wrow + koff + j * 8);
            }
            cp_commit();
        };

        issue(0); issue(1);
        cp_wait<1>();
        __syncthreads();

        for (int c = 0; c < nc; c++) {
            uint32_t st = sb + (c & 1) * STAGE;
#pragma unroll
            for (int ks = 0; ks < 4; ks++) {
                uint32_t ksel = (uint32_t)((2 * ks + csel) ^ x7) * 16;
                uint32_t ah[4][4], bh[4][2];
#pragma unroll
                for (int mi = 0; mi < 4; mi++)
                    ldmx4(ah[mi], st + AHI + arow_b[mi] + ksel);
#pragma unroll
                for (int nb = 0; nb < 2; nb++) {
                    uint32_t r[4];
                    ldmx4(r, st + WHI + wrow_b[nb] + ksel);
                    bh[2 * nb][0] = r[0]; bh[2 * nb + 1][0] = r[1];
                    bh[2 * nb][1] = r[2]; bh[2 * nb + 1][1] = r[3];
                }
#pragma unroll
                for (int mi = 0; mi < 4; mi++)
#pragma unroll
                    for (int ni = 0; ni < 4; ni++)
                        mma16816(acc[mi][ni], ah[mi], bh[ni]);
                uint32_t al[4][4], bl[4][2];
#pragma unroll
                for (int mi = 0; mi < 4; mi++)
                    ldmx4(al[mi], st + ALO + arow_b[mi] + ksel);
#pragma unroll
                for (int nb = 0; nb < 2; nb++) {
                    uint32_t r[4];
                    ldmx4(r, st + WLO + wrow_b[nb] + ksel);
                    bl[2 * nb][0] = r[0]; bl[2 * nb + 1][0] = r[1];
                    bl[2 * nb][1] = r[2]; bl[2 * nb + 1][1] = r[3];
                }
#pragma unroll
                for (int mi = 0; mi < 4; mi++)
#pragma unroll
                    for (int ni = 0; ni < 4; ni++) {
                        mma16816(acc[mi][ni], ah[mi], bl[ni]);
                        mma16816(acc[mi][ni], al[mi], bh[ni]);
                    }
            }
            __syncthreads();
            if (c + 2 < nc) issue(c + 2);
            else            cp_commit();
            cp_wait<1>();
            __syncthreads();
        }
    }

    const int lr4 = lane >> 2, lc2 = 2 * (lane & 3);
#pragma unroll
    for (int mi = 0; mi < 4; mi++) {
        int r0i = wm + mi * 16 + lr4;
        int r1i = r0i + 8;
        bool v0 = (row0 + r0i) < nrows;
        bool v1 = (row0 + r1i) < nrows;
        size_t g0 = (size_t)srow[r0i] * N + col0;
        size_t g1 = (size_t)srow[r1i] * N + col0;
#pragma unroll
        for (int ni = 0; ni < 4; ni++) {
            int cc = wn + ni * 8 + lc2;
            float ba = sbias[cc], bb = sbias[cc + 1];
            float x0 = acc[mi][ni][0] + ba, x1 = acc[mi][ni][1] + bb;
            float y0 = acc[mi][ni][2] + ba, y1 = acc[mi][ni][3] + bb;
            if (RELU) {
                x0 = fmaxf(x0, 0.0f); x1 = fmaxf(x1, 0.0f);
                y0 = fmaxf(y0, 0.0f); y1 = fmaxf(y1, 0.0f);
            }
            if (sizeof(OutT) == 4) {
                if (v0) *(float2*)((float*)C + g0 + cc) = make_float2(x0, x1);
                if (v1) *(float2*)((float*)C + g1 + cc) = make_float2(y0, y1);
            } else {
                uint32_t p0, p1;
                asm("cvt.rn.bf16x2.f32 %0, %1, %2;" : "=r"(p0) : "f"(x1), "f"(x0));
                asm("cvt.rn.bf16x2.f32 %0, %1, %2;" : "=r"(p1) : "f"(y1), "f"(y0));
                if (v0) *(uint32_t*)((bf16*)C + g0 + cc) = p0;
                if (v1) *(uint32_t*)((bf16*)C + g1 + cc) = p1;
            }
        }
    }
}

// --------- logits + argmax; scatter confident rows, flag marginal ones ---
__global__ void logits_argmax_kernel(const float* __restrict__ W3,
                                     const float* __restrict__ b3)
{
    __shared__ float sW[M_ * HH_];
    __shared__ float sb[M_];
    for (int i = threadIdx.x; i < M_ * HH_; i += blockDim.x) sW[i] = W3[i];
    if (threadIdx.x < M_) sb[threadIdx.x] = b3[threadIdx.x];
    __syncthreads();

    int gw   = (blockIdx.x * blockDim.x + threadIdx.x) >> 5;
    int lane = threadIdx.x & 31;
    int nw   = (gridDim.x * blockDim.x) >> 5;

    for (int row = gw; row < B_; row += nw) {
        const float* x = g_X1 + (size_t)row * HH_;
        float xv[16];
#pragma unroll
        for (int tt = 0; tt < 16; tt++) xv[tt] = x[lane + 32 * tt];
        float best = -3.0e38f, second = -3.0e38f;
        int   bi   = 0;
#pragma unroll
        for (int m = 0; m < M_; m++) {
            float p = 0.0f;
            const float* wrow = sW + m * HH_;
#pragma unroll
            for (int tt = 0; tt < 16; tt++)
                p = fmaf(xv[tt], wrow[lane + 32 * tt], p);
#pragma unroll
            for (int o = 16; o; o >>= 1) p += __shfl_xor_sync(0xffffffffu, p, o);
            p += sb[m];
            if (p > best) { second = best; best = p; bi = m; }
            else if (p > second) second = p;
        }
        if (lane == 0) {
            if (best - second >= MARGIN_THRESH) {
                int p = atomicAdd(&g_cnt[bi], 1);
                g_rows[bi * B_ + p] = row;
            } else {
                int fp = atomicAdd(&g_nflag, 1);
                g_flag[fp] = row;
            }
        }
    }
}

// --------- exact argmax for flagged rows (X1 now exact) + scatter -------
__global__ void logits_fix_kernel(const float* __restrict__ W3,
                                  const float* __restrict__ b3)
{
    __shared__ float sW[M_ * HH_];
    __shared__ float sb[M_];
    for (int i = threadIdx.x; i < M_ * HH_; i += blockDim.x) sW[i] = W3[i];
    if (threadIdx.x < M_) sb[threadIdx.x] = b3[threadIdx.x];
    __syncthreads();

    int gw   = (blockIdx.x * blockDim.x + threadIdx.x) >> 5;
    int lane = threadIdx.x & 31;
    int nw   = (gridDim.x * blockDim.x) >> 5;
    int nf   = g_nflag;

    for (int idx = gw; idx < nf; idx += nw) {
        int row = g_flag[idx];
        const float* x = g_X1 + (size_t)row * HH_;
        float xv[16];
#pragma unroll
        for (int tt = 0; tt < 16; tt++) xv[tt] = x[lane + 32 * tt];
        float best = -3.0e38f;
        int   bi   = 0;
#pragma unroll
        for (int m = 0; m < M_; m++) {
            float p = 0.0f;
            const float* wrow = sW + m * HH_;
#pragma unroll
            for (int tt = 0; tt < 16; tt++)
                p = fmaf(xv[tt], wrow[lane + 32 * tt], p);
#pragma unroll
            for (int o = 16; o; o >>= 1) p += __shfl_xor_sync(0xffffffffu, p, o);
            p += sb[m];
            if (p > best) { best = p; bi = m; }
        }
        if (lane == 0) {
            int p = atomicAdd(&g_cnt[bi], 1);
            g_rows[bi * B_ + p] = row;
        }
    }
}

__global__ void zero_kernel() {
    if (threadIdx.x < M_) g_cnt[threadIdx.x] = 0;
    if (threadIdx.x == M_) g_nflag = 0;
}

// out = O/max(||O||,eps) + Q   (O stored bf16)
__global__ void finalize_kernel(const float* __restrict__ Q, float* __restrict__ out)
{
    int row = blockIdx.x;
    const bf16* o = g_Ob16 + (size_t)row * H_;
    int t = threadIdx.x;

    float ov[4];
    {
        uint2 pk = *(const uint2*)(o + t * 4);
        __nv_bfloat162 a = *(__nv_bfloat162*)&pk.x;
        __nv_bfloat162 b = *(__nv_bfloat162*)&pk.y;
        ov[0] = __bfloat162float(a.x); ov[1] = __bfloat162float(a.y);
        ov[2] = __bfloat162float(b.x); ov[3] = __bfloat162float(b.y);
    }
    float s = ov[0]*ov[0] + ov[1]*ov[1] + ov[2]*ov[2] + ov[3]*ov[3];
#pragma unroll
    for (int off = 16; off; off >>= 1) s += __shfl_xor_sync(0xffffffffu, s, off);
    __shared__ float red[8];
    if ((t & 31) == 0) red[t >> 5] = s;
    __syncthreads();
    float tot = 0.0f;
#pragma unroll
    for (int w = 0; w < 8; w++) tot += red[w];
    float inv = 1.0f / fmaxf(sqrtf(tot), 1e-6f);

    float4 qv = *(const float4*)(Q + (size_t)row * H_ + t * 4);
    float4 r;
    r.x = fmaf(ov[0], inv, qv.x); r.y = fmaf(ov[1], inv, qv.y);
    r.z = fmaf(ov[2], inv, qv.z); r.w = fmaf(ov[3], inv, qv.w);
    *(float4*)(out + (size_t)row * H_ + t * 4) = r;
}

// ---------------- launch ----------------
extern "C" void kernel_launch(void* const* d_in, const int* in_sizes, int n_in,
                              void* d_out, int out_size)
{
    const float* q   = (const float*)d_in[0];
    const float* c1w = (const float*)d_in[1];
    const float* c1b = (const float*)d_in[2];
    const float* c3w = (const float*)d_in[3];
    const float* c3b = (const float*)d_in[4];
    const float* ew1 = (const float*)d_in[5];
    const float* eb1 = (const float*)d_in[6];
    const float* ew2 = (const float*)d_in[7];
    const float* eb2 = (const float*)d_in[8];
    float* out = (float*)d_out;

    void *pqh, *pql, *pw1h, *pw1l, *pe1, *pe2, *pX1, *pHb, *pO;
    cudaGetSymbolAddress(&pqh,  g_qhi);
    cudaGetSymbolAddress(&pql,  g_qlo);
    cudaGetSymbolAddress(&pw1h, g_w1hi);
    cudaGetSymbolAddress(&pw1l, g_w1lo);
    cudaGetSymbolAddress(&pe1,  g_ew1b);
    cudaGetSymbolAddress(&pe2,  g_ew2b);
    cudaGetSymbolAddress(&pX1,  g_X1);
    cudaGetSymbolAddress(&pHb,  g_Hb);
    cudaGetSymbolAddress(&pO,   g_Ob16);

    constexpr int SMEM_FAST  = 1024 + 3 * 2 * BM * 128;  // 99328
    constexpr int SMEM_SPLIT = 1024 + 2 * 4 * BM * 128;  // 132096

    cudaFuncSetAttribute(gemm_mma<0, 0, 1, float>,
                         cudaFuncAttributeMaxDynamicSharedMemorySize, SMEM_FAST);
    cudaFuncSetAttribute(gemm_mma<1, 2, 1, float>,
                         cudaFuncAttributeMaxDynamicSharedMemorySize, SMEM_SPLIT);
    cudaFuncSetAttribute(gemm_mma<0, 1, 1, bf16>,
                         cudaFuncAttributeMaxDynamicSharedMemorySize, SMEM_FAST);
    cudaFuncSetAttribute(gemm_mma<0, 1, 0, bf16>,
                         cudaFuncAttributeMaxDynamicSharedMemorySize, SMEM_FAST);

    // 1) q -> bf16 hi only
    cvt16_k<<<B_ * H_ / 16 / 256, 256>>>(q, (bf16*)pqh, B_ * H_);
    // 2) w1 -> hi/lo (lo used by the exact fallback)
    split16_k<<<HH_ * H_ / 16 / 256, 256>>>(c1w, (bf16*)pw1h, (bf16*)pw1l, HH_ * H_);
    // 3) zero counters
    zero_kernel<<<1, 32>>>();
    // 4) gating hidden (single-pass bf16)  <-- ncu profile slot
    gemm_mma<0, 0, 1, float><<<dim3(B_ / BM, HH_ / BN, 1), NTH, SMEM_FAST>>>(
        (const bf16*)pqh, nullptr, (const bf16*)pw1h, nullptr,
        c1b, (float*)pX1, HH_, H_, B_);
    // 5) logits + argmax: scatter confident, flag marginal
    logits_argmax_kernel<<<64, 256>>>(c3w, c3b);
    // 6) qlo for flagged rows
    qlo_flag_k<<<64, 256>>>(q);
    // 7) exact (3-pass) X1 recompute for flagged rows
    gemm_mma<1, 2, 1, float><<<dim3(B_ / BM, HH_ / BN, 1), NTH, SMEM_SPLIT>>>(
        (const bf16*)pqh, (const bf16*)pql, (const bf16*)pw1h, (const bf16*)pw1l,
        c1b, (float*)pX1, HH_, H_, 0);
    // 8) exact argmax + scatter for flagged rows
    logits_fix_kernel<<<32, 256>>>(c3w, c3b);
    // 9,10) expert weights -> bf16
    cvt16_k<<<M_ * HH_ * H_ / 16 / 256, 256>>>(ew1, (bf16*)pe1, M_ * HH_ * H_);
    cvt16_k<<<M_ * H_ * HH_ / 16 / 256, 256>>>(ew2, (bf16*)pe2, M_ * H_ * HH_);
    // 11) expert hidden: H = relu(Qg @ ew1[m]^T + b1[m])  (bf16 out)
    gemm_mma<0, 1, 1, bf16><<<dim3(B_ / BM, HH_ / BN, M_), NTH, SMEM_FAST>>>(
        (const bf16*)pqh, nullptr, (const bf16*)pe1, nullptr,
        eb1, (bf16*)pHb, HH_, H_, 0);
    // 12) expert out: O = Hg @ ew2[m]^T + b2[m]  (bf16 out)
    gemm_mma<0, 1, 0, bf16><<<dim3(B_ / BM, H_ / BN, M_), NTH, SMEM_FAST>>>(
        (const bf16*)pHb, nullptr, (const bf16*)pe2, nullptr,
        eb2, (bf16*)pO, H_, HH_, 0);
    // 13) out = normalize(O) + Q
    finalize_kernel<<<B_, 256>>>(q, out);
}